// round 1
// baseline (speedup 1.0000x reference)
#include <cuda_runtime.h>
#include <math.h>

#define D_MODEL 1024
#define NHEADS  16
#define DK      64
#define DFF     4096
#define SEQ     2048
#define BATCH   2
#define T_TOK   (BATCH * SEQ)                 /* 4096 tokens */

#define OUT_ELEMS  ((long)T_TOK * D_MODEL)                  /* 4,194,304   */
#define ATTN_ELEMS ((long)BATCH * NHEADS * SEQ * SEQ)       /* 134,217,728 */

/* ------------------------------------------------------------------ */
/* Scratch (allocation-free: __device__ globals)                       */
/* ------------------------------------------------------------------ */
__device__ float g_Q  [T_TOK * D_MODEL];
__device__ float g_K  [T_TOK * D_MODEL];
__device__ float g_V  [T_TOK * D_MODEL];
__device__ float g_ctx[T_TOK * D_MODEL];
__device__ float g_h  [T_TOK * D_MODEL];
__device__ float g_res[T_TOK * D_MODEL];
__device__ float g_ff [T_TOK * DFF];

/* ------------------------------------------------------------------ */
/* Generic tiled fp32 GEMM: C = alpha * A @ B(^T) [+ epilogue]         */
/*   BM=BN=128, BK=8, 256 threads, 8x8 per-thread micro-tile           */
/*   EPI: 0 = none, 2 = +bias +residual, 3 = gelu(+bias)               */
/*   Batched over z with (b,h) decomposition when Hdiv > 0             */
/* ------------------------------------------------------------------ */
__device__ __forceinline__ float gelu_exact(float x) {
    return 0.5f * x * (1.0f + erff(x * 0.70710678118654752440f));
}

template <bool TRANSB, int EPI>
__global__ void __launch_bounds__(256)
gemm_k(const float* __restrict__ A, const float* __restrict__ B,
       float* __restrict__ C,
       int M, int N, int K, int lda, int ldb, int ldc,
       long sAb, long sAh, long sBb, long sBh, long sCb, long sCh, int Hdiv,
       const float* __restrict__ bias, const float* __restrict__ resid,
       float alpha)
{
    if (Hdiv > 0) {
        int z = blockIdx.z;
        int b = z / Hdiv, h = z % Hdiv;
        A += (long)b * sAb + (long)h * sAh;
        B += (long)b * sBb + (long)h * sBh;
        C += (long)b * sCb + (long)h * sCh;
    }

    __shared__ float As[8][128];
    __shared__ float Bs[8][128];

    const int tx = threadIdx.x;           /* 0..15 */
    const int ty = threadIdx.y;           /* 0..15 */
    const int t  = ty * 16 + tx;          /* 0..255 */
    const int row0 = blockIdx.y * 128;
    const int col0 = blockIdx.x * 128;

    float acc[8][8];
#pragma unroll
    for (int i = 0; i < 8; i++)
#pragma unroll
        for (int j = 0; j < 8; j++) acc[i][j] = 0.0f;

    /* A tile: 128 rows x 8 cols, one float4 per thread */
    const int aRow = t >> 1;
    const int aCol = (t & 1) * 4;
    /* B tile mapping */
    const int bR_t = t >> 1;              /* TRANSB: n-index   */
    const int bC_t = (t & 1) * 4;         /* TRANSB: k-offset  */
    const int bR_n = t >> 5;              /* !TRANSB: k-index  */
    const int bC_n = (t & 31) * 4;        /* !TRANSB: n-offset */

    for (int k0 = 0; k0 < K; k0 += 8) {
        /* load A (M always a multiple of 128, K multiple of 8) */
        float4 av = *(const float4*)&A[(long)(row0 + aRow) * lda + k0 + aCol];
        As[aCol + 0][aRow] = av.x;
        As[aCol + 1][aRow] = av.y;
        As[aCol + 2][aRow] = av.z;
        As[aCol + 3][aRow] = av.w;

        if (TRANSB) {
            float4 bv = make_float4(0.f, 0.f, 0.f, 0.f);
            if (col0 + bR_t < N)
                bv = *(const float4*)&B[(long)(col0 + bR_t) * ldb + k0 + bC_t];
            Bs[bC_t + 0][bR_t] = bv.x;
            Bs[bC_t + 1][bR_t] = bv.y;
            Bs[bC_t + 2][bR_t] = bv.z;
            Bs[bC_t + 3][bR_t] = bv.w;
        } else {
            float4 bv = make_float4(0.f, 0.f, 0.f, 0.f);
            if (col0 + bC_n < N)
                bv = *(const float4*)&B[(long)(k0 + bR_n) * ldb + col0 + bC_n];
            *(float4*)&Bs[bR_n][bC_n] = bv;
        }
        __syncthreads();

#pragma unroll
        for (int kk = 0; kk < 8; kk++) {
            float a[8], b[8];
#pragma unroll
            for (int i = 0; i < 8; i++) a[i] = As[kk][ty * 8 + i];
#pragma unroll
            for (int j = 0; j < 8; j++) b[j] = Bs[kk][tx * 8 + j];
#pragma unroll
            for (int i = 0; i < 8; i++)
#pragma unroll
                for (int j = 0; j < 8; j++)
                    acc[i][j] = fmaf(a[i], b[j], acc[i][j]);
        }
        __syncthreads();
    }

#pragma unroll
    for (int i = 0; i < 8; i++) {
        const int row = row0 + ty * 8 + i;
#pragma unroll
        for (int j = 0; j < 8; j++) {
            const int col = col0 + tx * 8 + j;
            if (col < N) {
                float v = acc[i][j] * alpha;
                if (EPI == 2) v += bias[col] + resid[(long)row * ldc + col];
                else if (EPI == 3) v = gelu_exact(v + bias[col]);
                C[(long)row * ldc + col] = v;
            }
        }
    }
}

/* ------------------------------------------------------------------ */
/* Row softmax over SEQ=2048 entries, register-resident               */
/* ------------------------------------------------------------------ */
__global__ void __launch_bounds__(256)
softmax_k(float* __restrict__ attn)
{
    float* row = attn + (long)blockIdx.x * SEQ;
    const int tid = threadIdx.x;
    __shared__ float red[256];

    float v[8];
    float m = -1e30f;
#pragma unroll
    for (int j = 0; j < 8; j++) {
        v[j] = row[tid + j * 256];
        m = fmaxf(m, v[j]);
    }
    red[tid] = m;
    __syncthreads();
    for (int s = 128; s > 0; s >>= 1) {
        if (tid < s) red[tid] = fmaxf(red[tid], red[tid + s]);
        __syncthreads();
    }
    m = red[0];
    __syncthreads();

    float sum = 0.0f;
#pragma unroll
    for (int j = 0; j < 8; j++) {
        v[j] = expf(v[j] - m);
        sum += v[j];
    }
    red[tid] = sum;
    __syncthreads();
    for (int s = 128; s > 0; s >>= 1) {
        if (tid < s) red[tid] += red[tid + s];
        __syncthreads();
    }
    const float inv = 1.0f / red[0];

#pragma unroll
    for (int j = 0; j < 8; j++)
        row[tid + j * 256] = v[j] * inv;
}

/* ------------------------------------------------------------------ */
/* LayerNorm over D_MODEL=1024, one block per token                   */
/* ------------------------------------------------------------------ */
__global__ void __launch_bounds__(256)
layernorm_k(const float* __restrict__ in, float* __restrict__ out,
            const float* __restrict__ gamma, const float* __restrict__ beta)
{
    const float* row = in + (long)blockIdx.x * D_MODEL;
    float*       orow = out + (long)blockIdx.x * D_MODEL;
    const int tid = threadIdx.x;
    __shared__ float red[256];

    float v[4];
    float s = 0.0f;
#pragma unroll
    for (int j = 0; j < 4; j++) {
        v[j] = row[tid + j * 256];
        s += v[j];
    }
    red[tid] = s;
    __syncthreads();
    for (int st = 128; st > 0; st >>= 1) {
        if (tid < st) red[tid] += red[tid + st];
        __syncthreads();
    }
    const float mu = red[0] * (1.0f / D_MODEL);
    __syncthreads();

    float vs = 0.0f;
#pragma unroll
    for (int j = 0; j < 4; j++) {
        float d = v[j] - mu;
        vs += d * d;
    }
    red[tid] = vs;
    __syncthreads();
    for (int st = 128; st > 0; st >>= 1) {
        if (tid < st) red[tid] += red[tid + st];
        __syncthreads();
    }
    const float inv = rsqrtf(red[0] * (1.0f / D_MODEL) + 1e-5f);

#pragma unroll
    for (int j = 0; j < 4; j++) {
        const int c = tid + j * 256;
        orow[c] = (v[j] - mu) * inv * gamma[c] + beta[c];
    }
}

/* ------------------------------------------------------------------ */
/* Launch                                                              */
/* ------------------------------------------------------------------ */
extern "C" void kernel_launch(void* const* d_in, const int* in_sizes, int n_in,
                              void* d_out, int out_size)
{
    const float* x    = (const float*)d_in[0];
    const float* w_q  = (const float*)d_in[1];
    const float* w_k  = (const float*)d_in[2];
    const float* w_v  = (const float*)d_in[3];
    const float* w_o  = (const float*)d_in[4];
    const float* b_o  = (const float*)d_in[5];
    const float* w1   = (const float*)d_in[6];
    const float* b1   = (const float*)d_in[7];
    const float* w2   = (const float*)d_in[8];
    const float* b2   = (const float*)d_in[9];
    const float* ln1g = (const float*)d_in[10];
    const float* ln1b = (const float*)d_in[11];
    const float* ln2g = (const float*)d_in[12];
    const float* ln2b = (const float*)d_in[13];

    float* out  = (float*)d_out;
    float* attn = out + OUT_ELEMS;

    float *Q, *K, *V, *ctx, *h, *res, *ff;
    { void* p; cudaGetSymbolAddress(&p, g_Q);   Q   = (float*)p; }
    { void* p; cudaGetSymbolAddress(&p, g_K);   K   = (float*)p; }
    { void* p; cudaGetSymbolAddress(&p, g_V);   V   = (float*)p; }
    { void* p; cudaGetSymbolAddress(&p, g_ctx); ctx = (float*)p; }
    { void* p; cudaGetSymbolAddress(&p, g_h);   h   = (float*)p; }
    { void* p; cudaGetSymbolAddress(&p, g_res); res = (float*)p; }
    { void* p; cudaGetSymbolAddress(&p, g_ff);  ff  = (float*)p; }

    dim3 blk(16, 16);

    /* 1) Q, K, V projections: [4096,1024] @ [1024,1024] */
    dim3 gqkv(D_MODEL / 128, T_TOK / 128, 1);
    gemm_k<false, 0><<<gqkv, blk>>>(x, w_q, Q, T_TOK, D_MODEL, D_MODEL,
                                    D_MODEL, D_MODEL, D_MODEL,
                                    0, 0, 0, 0, 0, 0, 0, nullptr, nullptr, 1.0f);
    gemm_k<false, 0><<<gqkv, blk>>>(x, w_k, K, T_TOK, D_MODEL, D_MODEL,
                                    D_MODEL, D_MODEL, D_MODEL,
                                    0, 0, 0, 0, 0, 0, 0, nullptr, nullptr, 1.0f);
    gemm_k<false, 0><<<gqkv, blk>>>(x, w_v, V, T_TOK, D_MODEL, D_MODEL,
                                    D_MODEL, D_MODEL, D_MODEL,
                                    0, 0, 0, 0, 0, 0, 0, nullptr, nullptr, 1.0f);

    /* 2) scores = Q @ K^T / sqrt(dk), batched over (b,h) -> attn region */
    {
        dim3 g(SEQ / 128, SEQ / 128, BATCH * NHEADS);
        gemm_k<true, 0><<<g, blk>>>(Q, K, attn, SEQ, SEQ, DK,
                                    D_MODEL, D_MODEL, SEQ,
                                    (long)SEQ * D_MODEL, (long)DK,
                                    (long)SEQ * D_MODEL, (long)DK,
                                    (long)NHEADS * SEQ * SEQ, (long)SEQ * SEQ,
                                    NHEADS, nullptr, nullptr, 0.125f);
    }

    /* 3) softmax rows (in place in d_out attn region) */
    softmax_k<<<BATCH * NHEADS * SEQ, 256>>>(attn);

    /* 4) context = attn @ V, batched; scattered back into [B,S,H*dk] */
    {
        dim3 g(1, SEQ / 128, BATCH * NHEADS);
        gemm_k<false, 0><<<g, blk>>>(attn, V, ctx, SEQ, DK, SEQ,
                                     SEQ, D_MODEL, D_MODEL,
                                     (long)NHEADS * SEQ * SEQ, (long)SEQ * SEQ,
                                     (long)SEQ * D_MODEL, (long)DK,
                                     (long)SEQ * D_MODEL, (long)DK,
                                     NHEADS, nullptr, nullptr, 1.0f);
    }

    /* 5) attn_out = ctx @ w_o + b_o + x  -> res */
    dim3 gproj(D_MODEL / 128, T_TOK / 128, 1);
    gemm_k<false, 2><<<gproj, blk>>>(ctx, w_o, res, T_TOK, D_MODEL, D_MODEL,
                                     D_MODEL, D_MODEL, D_MODEL,
                                     0, 0, 0, 0, 0, 0, 0, b_o, x, 1.0f);

    /* 6) h = LN1(res) */
    layernorm_k<<<T_TOK, 256>>>(res, h, ln1g, ln1b);

    /* 7) ff = gelu(h @ w1 + b1) : [4096,1024]@[1024,4096] */
    {
        dim3 g(DFF / 128, T_TOK / 128, 1);
        gemm_k<false, 3><<<g, blk>>>(h, w1, ff, T_TOK, DFF, D_MODEL,
                                     D_MODEL, DFF, DFF,
                                     0, 0, 0, 0, 0, 0, 0, b1, nullptr, 1.0f);
    }

    /* 8) res = ff @ w2 + b2 + h : [4096,4096]@[4096,1024] */
    gemm_k<false, 2><<<gproj, blk>>>(ff, w2, res, T_TOK, D_MODEL, DFF,
                                     DFF, D_MODEL, D_MODEL,
                                     0, 0, 0, 0, 0, 0, 0, b2, h, 1.0f);

    /* 9) out = LN2(res) */
    layernorm_k<<<T_TOK, 256>>>(res, out, ln2g, ln2b);
}

// round 3
// speedup vs baseline: 1.1356x; 1.1356x over previous
#include <cuda_runtime.h>
#include <math.h>
#include <stdint.h>

#define D_MODEL 1024
#define NHEADS  16
#define DK      64
#define DFF     4096
#define SEQ     2048
#define BATCH   2
#define T_TOK   (BATCH * SEQ)                 /* 4096 tokens */

#define OUT_ELEMS  ((long)T_TOK * D_MODEL)                  /* 4,194,304   */

/* ------------------------------------------------------------------ */
/* Scratch (allocation-free: __device__ globals)                       */
/* ------------------------------------------------------------------ */
__device__ float g_Q  [T_TOK * D_MODEL];
__device__ float g_K  [T_TOK * D_MODEL];
__device__ float g_V  [T_TOK * D_MODEL];
__device__ float g_ctx[T_TOK * D_MODEL];
__device__ float g_h  [T_TOK * D_MODEL];
__device__ float g_res[T_TOK * D_MODEL];
__device__ float g_ff [T_TOK * DFF];

/* ------------------------------------------------------------------ */
/* Helpers                                                             */
/* ------------------------------------------------------------------ */
__device__ __forceinline__ float gelu_exact(float x) {
    return 0.5f * x * (1.0f + erff(x * 0.70710678118654752440f));
}

__device__ __forceinline__ float to_tf32(float x) {
    uint32_t u;
    asm("cvt.rna.tf32.f32 %0, %1;" : "=r"(u) : "f"(x));
    return __uint_as_float(u);
}

__device__ __forceinline__ void mma_tf32(float* d, const float* a, float b0, float b1) {
    const uint32_t* A = reinterpret_cast<const uint32_t*>(a);
    uint32_t B0 = __float_as_uint(b0), B1 = __float_as_uint(b1);
    asm volatile(
        "mma.sync.aligned.m16n8k8.row.col.f32.tf32.tf32.f32 "
        "{%0,%1,%2,%3}, {%4,%5,%6,%7}, {%8,%9}, {%0,%1,%2,%3};\n"
        : "+f"(d[0]), "+f"(d[1]), "+f"(d[2]), "+f"(d[3])
        : "r"(A[0]), "r"(A[1]), "r"(A[2]), "r"(A[3]), "r"(B0), "r"(B1));
}

/* ------------------------------------------------------------------ */
/* TF32 tensor-core GEMM: C = alpha * A @ B(^T) [+ epilogue]           */
/*   BM=BN=128, BK=16, 256 threads (8 warps, 4x2), warp tile 32x64     */
/*   EPI: 0 = none, 2 = +bias +residual, 3 = gelu(+bias)               */
/* ------------------------------------------------------------------ */
template <bool TRANSB, int EPI>
__global__ void __launch_bounds__(256, 2)
gemm_tc(const float* __restrict__ A, const float* __restrict__ B,
        float* __restrict__ C,
        int M, int N, int K, int lda, int ldb, int ldc,
        long sAb, long sAh, long sBb, long sBh, long sCb, long sCh, int Hdiv,
        const float* __restrict__ bias, const float* __restrict__ resid,
        float alpha)
{
    if (Hdiv > 0) {
        int z = blockIdx.z;
        int b = z / Hdiv, h = z % Hdiv;
        A += (long)b * sAb + (long)h * sAh;
        B += (long)b * sBb + (long)h * sBh;
        C += (long)b * sCb + (long)h * sCh;
    }

    /* As: plain [m][k], stride 20 (conflict-free scalar frag loads)    */
    /* Bs: [n][k'] k-permuted (k'=(k%4)*4+k/4), XOR-swizzled float4s    */
    __shared__ float As[128][20];
    __shared__ float Bs[128][16];

    const int t    = threadIdx.x;
    const int w    = t >> 5;
    const int lane = t & 31;
    const int wm   = w & 3;            /* warp row 0..3  */
    const int wn   = w >> 2;           /* warp col 0..1  */
    const int r    = lane >> 2;        /* 0..7 */
    const int c    = lane & 3;         /* 0..3 */
    const int row0 = blockIdx.y * 128;
    const int col0 = blockIdx.x * 128;

    float acc[2][8][4];
#pragma unroll
    for (int i = 0; i < 2; i++)
#pragma unroll
        for (int j = 0; j < 8; j++)
#pragma unroll
            for (int q = 0; q < 4; q++) acc[i][j][q] = 0.0f;

    /* A tile loader: consecutive threads -> consecutive rows (no STS
       bank collisions within a quad); each thread owns one float4.    */
    const int aRow = t & 127;          /* 0..127 */
    const int aF4  = t >> 7;           /* 0..1   */

    for (int k0 = 0; k0 < K; k0 += 16) {
        /* ---- load A tile: 128 x 16 (M always multiple of 128) ---- */
#pragma unroll
        for (int it = 0; it < 2; it++) {
            int f4 = aF4 + it * 2;     /* 0..3 */
            float4 v = *(const float4*)&A[(long)(row0 + aRow) * lda + k0 + f4 * 4];
            As[aRow][f4 * 4 + 0] = to_tf32(v.x);
            As[aRow][f4 * 4 + 1] = to_tf32(v.y);
            As[aRow][f4 * 4 + 2] = to_tf32(v.z);
            As[aRow][f4 * 4 + 3] = to_tf32(v.w);
        }

        /* ---- load B tile into Bs[n][k'] ---- */
        if (TRANSB) {
            /* B global: [N][K] row-major; read float4 along k */
#pragma unroll
            for (int it = 0; it < 2; it++) {
                int n  = aRow;
                int f4 = aF4 + it * 2;
                float4 v = make_float4(0.f, 0.f, 0.f, 0.f);
                if (col0 + n < N)
                    v = *(const float4*)&B[(long)(col0 + n) * ldb + k0 + f4 * 4];
                int sw = n & 3;
                /* k = f4*4 + j  ->  k' = j*4 + f4; phys = (j^sw)*4 + f4 */
                Bs[n][((0 ^ sw) << 2) + f4] = to_tf32(v.x);
                Bs[n][((1 ^ sw) << 2) + f4] = to_tf32(v.y);
                Bs[n][((2 ^ sw) << 2) + f4] = to_tf32(v.z);
                Bs[n][((3 ^ sw) << 2) + f4] = to_tf32(v.w);
            }
        } else {
            /* B global: [K][N] row-major; read float4 along n */
#pragma unroll
            for (int it = 0; it < 2; it++) {
                int idx = t + it * 256;
                int k   = idx >> 5;            /* 0..15 */
                int nf4 = idx & 31;
                int n   = nf4 * 4;
                float4 v = make_float4(0.f, 0.f, 0.f, 0.f);
                if (col0 + n < N)
                    v = *(const float4*)&B[(long)(k0 + k) * ldb + col0 + n];
                int km = k & 3, kd = k >> 2;
                /* phys for col nn: ((k%4) ^ (nn&3))*4 + k/4 */
                Bs[n + 0][((km ^ ((n + 0) & 3)) << 2) + kd] = to_tf32(v.x);
                Bs[n + 1][((km ^ ((n + 1) & 3)) << 2) + kd] = to_tf32(v.y);
                Bs[n + 2][((km ^ ((n + 2) & 3)) << 2) + kd] = to_tf32(v.z);
                Bs[n + 3][((km ^ ((n + 3) & 3)) << 2) + kd] = to_tf32(v.w);
            }
        }
        __syncthreads();

        /* ---- fragments + MMA ---- */
        float a[2][2][4];
#pragma unroll
        for (int i = 0; i < 2; i++) {
            int m0 = wm * 32 + i * 16 + r;
#pragma unroll
            for (int s = 0; s < 2; s++) {
                int kc = s * 8 + c;
                a[i][s][0] = As[m0][kc];
                a[i][s][1] = As[m0 + 8][kc];
                a[i][s][2] = As[m0][kc + 4];
                a[i][s][3] = As[m0 + 8][kc + 4];
            }
        }
#pragma unroll
        for (int j = 0; j < 8; j++) {
            int n = wn * 64 + j * 8 + r;
            float4 bv = *(const float4*)&Bs[n][(c ^ (n & 3)) << 2];
#pragma unroll
            for (int i = 0; i < 2; i++) {
                mma_tf32(acc[i][j], a[i][0], bv.x, bv.y);
                mma_tf32(acc[i][j], a[i][1], bv.z, bv.w);
            }
        }
        __syncthreads();
    }

    /* ---- epilogue ---- */
#pragma unroll
    for (int i = 0; i < 2; i++) {
#pragma unroll
        for (int j = 0; j < 8; j++) {
            int row = row0 + wm * 32 + i * 16 + r;
            int col = col0 + wn * 64 + j * 8 + c * 2;
            if (col < N) {
#pragma unroll
                for (int half = 0; half < 2; half++) {
                    int rr = row + half * 8;
                    float v0 = acc[i][j][half * 2 + 0] * alpha;
                    float v1 = acc[i][j][half * 2 + 1] * alpha;
                    if (EPI == 2) {
                        v0 += bias[col]     + resid[(long)rr * ldc + col];
                        v1 += bias[col + 1] + resid[(long)rr * ldc + col + 1];
                    } else if (EPI == 3) {
                        v0 = gelu_exact(v0 + bias[col]);
                        v1 = gelu_exact(v1 + bias[col + 1]);
                    }
                    *(float2*)&C[(long)rr * ldc + col] = make_float2(v0, v1);
                }
            }
        }
    }
}

/* ------------------------------------------------------------------ */
/* Row softmax over SEQ=2048 entries, register-resident               */
/* ------------------------------------------------------------------ */
__global__ void __launch_bounds__(256)
softmax_k(float* __restrict__ attn)
{
    float* row = attn + (long)blockIdx.x * SEQ;
    const int tid = threadIdx.x;
    __shared__ float red[256];

    float v[8];
    float m = -1e30f;
#pragma unroll
    for (int j = 0; j < 8; j++) {
        v[j] = row[tid + j * 256];
        m = fmaxf(m, v[j]);
    }
    red[tid] = m;
    __syncthreads();
    for (int s = 128; s > 0; s >>= 1) {
        if (tid < s) red[tid] = fmaxf(red[tid], red[tid + s]);
        __syncthreads();
    }
    m = red[0];
    __syncthreads();

    float sum = 0.0f;
#pragma unroll
    for (int j = 0; j < 8; j++) {
        v[j] = expf(v[j] - m);
        sum += v[j];
    }
    red[tid] = sum;
    __syncthreads();
    for (int s = 128; s > 0; s >>= 1) {
        if (tid < s) red[tid] += red[tid + s];
        __syncthreads();
    }
    const float inv = 1.0f / red[0];

#pragma unroll
    for (int j = 0; j < 8; j++)
        row[tid + j * 256] = v[j] * inv;
}

/* ------------------------------------------------------------------ */
/* LayerNorm over D_MODEL=1024, one block per token                   */
/* ------------------------------------------------------------------ */
__global__ void __launch_bounds__(256)
layernorm_k(const float* __restrict__ in, float* __restrict__ out,
            const float* __restrict__ gamma, const float* __restrict__ beta)
{
    const float* row = in + (long)blockIdx.x * D_MODEL;
    float*       orow = out + (long)blockIdx.x * D_MODEL;
    const int tid = threadIdx.x;
    __shared__ float red[256];

    float v[4];
    float s = 0.0f;
#pragma unroll
    for (int j = 0; j < 4; j++) {
        v[j] = row[tid + j * 256];
        s += v[j];
    }
    red[tid] = s;
    __syncthreads();
    for (int st = 128; st > 0; st >>= 1) {
        if (tid < st) red[tid] += red[tid + st];
        __syncthreads();
    }
    const float mu = red[0] * (1.0f / D_MODEL);
    __syncthreads();

    float vs = 0.0f;
#pragma unroll
    for (int j = 0; j < 4; j++) {
        float d = v[j] - mu;
        vs += d * d;
    }
    red[tid] = vs;
    __syncthreads();
    for (int st = 128; st > 0; st >>= 1) {
        if (tid < st) red[tid] += red[tid + st];
        __syncthreads();
    }
    const float inv = rsqrtf(red[0] * (1.0f / D_MODEL) + 1e-5f);

#pragma unroll
    for (int j = 0; j < 4; j++) {
        const int c = tid + j * 256;
        orow[c] = (v[j] - mu) * inv * gamma[c] + beta[c];
    }
}

/* ------------------------------------------------------------------ */
/* Launch                                                              */
/* ------------------------------------------------------------------ */
extern "C" void kernel_launch(void* const* d_in, const int* in_sizes, int n_in,
                              void* d_out, int out_size)
{
    const float* x    = (const float*)d_in[0];
    const float* w_q  = (const float*)d_in[1];
    const float* w_k  = (const float*)d_in[2];
    const float* w_v  = (const float*)d_in[3];
    const float* w_o  = (const float*)d_in[4];
    const float* b_o  = (const float*)d_in[5];
    const float* w1   = (const float*)d_in[6];
    const float* b1   = (const float*)d_in[7];
    const float* w2   = (const float*)d_in[8];
    const float* b2   = (const float*)d_in[9];
    const float* ln1g = (const float*)d_in[10];
    const float* ln1b = (const float*)d_in[11];
    const float* ln2g = (const float*)d_in[12];
    const float* ln2b = (const float*)d_in[13];

    float* out  = (float*)d_out;
    float* attn = out + OUT_ELEMS;

    float *Q, *K, *V, *ctx, *h, *res, *ff;
    { void* p; cudaGetSymbolAddress(&p, g_Q);   Q   = (float*)p; }
    { void* p; cudaGetSymbolAddress(&p, g_K);   K   = (float*)p; }
    { void* p; cudaGetSymbolAddress(&p, g_V);   V   = (float*)p; }
    { void* p; cudaGetSymbolAddress(&p, g_ctx); ctx = (float*)p; }
    { void* p; cudaGetSymbolAddress(&p, g_h);   h   = (float*)p; }
    { void* p; cudaGetSymbolAddress(&p, g_res); res = (float*)p; }
    { void* p; cudaGetSymbolAddress(&p, g_ff);  ff  = (float*)p; }

    dim3 blk(256);

    /* 1) Q, K, V projections: [4096,1024] @ [1024,1024] */
    dim3 gqkv(D_MODEL / 128, T_TOK / 128, 1);
    gemm_tc<false, 0><<<gqkv, blk>>>(x, w_q, Q, T_TOK, D_MODEL, D_MODEL,
                                     D_MODEL, D_MODEL, D_MODEL,
                                     0, 0, 0, 0, 0, 0, 0, nullptr, nullptr, 1.0f);
    gemm_tc<false, 0><<<gqkv, blk>>>(x, w_k, K, T_TOK, D_MODEL, D_MODEL,
                                     D_MODEL, D_MODEL, D_MODEL,
                                     0, 0, 0, 0, 0, 0, 0, nullptr, nullptr, 1.0f);
    gemm_tc<false, 0><<<gqkv, blk>>>(x, w_v, V, T_TOK, D_MODEL, D_MODEL,
                                     D_MODEL, D_MODEL, D_MODEL,
                                     0, 0, 0, 0, 0, 0, 0, nullptr, nullptr, 1.0f);

    /* 2) scores = Q @ K^T / sqrt(dk), batched over (b,h) -> attn region */
    {
        dim3 g(SEQ / 128, SEQ / 128, BATCH * NHEADS);
        gemm_tc<true, 0><<<g, blk>>>(Q, K, attn, SEQ, SEQ, DK,
                                     D_MODEL, D_MODEL, SEQ,
                                     (long)SEQ * D_MODEL, (long)DK,
                                     (long)SEQ * D_MODEL, (long)DK,
                                     (long)NHEADS * SEQ * SEQ, (long)SEQ * SEQ,
                                     NHEADS, nullptr, nullptr, 0.125f);
    }

    /* 3) softmax rows (in place in d_out attn region) */
    softmax_k<<<BATCH * NHEADS * SEQ, 256>>>(attn);

    /* 4) context = attn @ V, batched; scattered back into [B,S,H*dk] */
    {
        dim3 g(1, SEQ / 128, BATCH * NHEADS);
        gemm_tc<false, 0><<<g, blk>>>(attn, V, ctx, SEQ, DK, SEQ,
                                      SEQ, D_MODEL, D_MODEL,
                                      (long)NHEADS * SEQ * SEQ, (long)SEQ * SEQ,
                                      (long)SEQ * D_MODEL, (long)DK,
                                      (long)SEQ * D_MODEL, (long)DK,
                                      NHEADS, nullptr, nullptr, 1.0f);
    }

    /* 5) attn_out = ctx @ w_o + b_o + x  -> res */
    dim3 gproj(D_MODEL / 128, T_TOK / 128, 1);
    gemm_tc<false, 2><<<gproj, blk>>>(ctx, w_o, res, T_TOK, D_MODEL, D_MODEL,
                                      D_MODEL, D_MODEL, D_MODEL,
                                      0, 0, 0, 0, 0, 0, 0, b_o, x, 1.0f);

    /* 6) h = LN1(res) */
    layernorm_k<<<T_TOK, 256>>>(res, h, ln1g, ln1b);

    /* 7) ff = gelu(h @ w1 + b1) : [4096,1024]@[1024,4096] */
    {
        dim3 g(DFF / 128, T_TOK / 128, 1);
        gemm_tc<false, 3><<<g, blk>>>(h, w1, ff, T_TOK, DFF, D_MODEL,
                                      D_MODEL, DFF, DFF,
                                      0, 0, 0, 0, 0, 0, 0, b1, nullptr, 1.0f);
    }

    /* 8) res = ff @ w2 + b2 + h : [4096,4096]@[4096,1024] */
    gemm_tc<false, 2><<<gproj, blk>>>(ff, w2, res, T_TOK, D_MODEL, DFF,
                                      DFF, D_MODEL, D_MODEL,
                                      0, 0, 0, 0, 0, 0, 0, b2, h, 1.0f);

    /* 9) out = LN2(res) */
    layernorm_k<<<T_TOK, 256>>>(res, out, ln2g, ln2b);
}